// round 11
// baseline (speedup 1.0000x reference)
#include <cuda_runtime.h>

#define NB 1024
#define NS 50
#define NH 64
#define NITEM 40000
#define TPB 256
#define NQ (NB / 2)       // 512 CTAs, 2 rows each

typedef unsigned long long u64;

__device__ __forceinline__ u64 pk(float lo, float hi) {
    u64 r; asm("mov.b64 %0, {%1, %2};" : "=l"(r) : "f"(lo), "f"(hi)); return r;
}
__device__ __forceinline__ void fma2(u64& d, u64 a, u64 b) {
    asm("fma.rn.f32x2 %0, %1, %2, %0;" : "+l"(d) : "l"(a), "l"(b));
}
__device__ __forceinline__ void add2(u64& d, u64 a) {
    asm("add.rn.f32x2 %0, %1, %0;" : "+l"(d) : "l"(a));
}
__device__ __forceinline__ float hsum2(u64 v) {
    float lo, hi; asm("mov.b64 {%0, %1}, %2;" : "=f"(lo), "=f"(hi) : "l"(v));
    return lo + hi;
}

__global__ __launch_bounds__(TPB, 3)
void rrd_all(const float* __restrict__ all_memory,
             const float* __restrict__ last_memory,
             const int*   __restrict__ seq_item,
             const float* __restrict__ Wr,
             const float* __restrict__ Ur,
             const float* __restrict__ Vr_w,
             float* __restrict__ out)
{
    const int q   = blockIdx.x;
    const int b0  = 2 * q;
    const int tid = threadIdx.x;

    __shared__ __align__(16) float xs[2 * NS * NH];   // 25.6 KB
    __shared__ __align__(16) float mat[NH * NH];      // 16.4 KB, XOR-swizzled float4 rows
    __shared__ __align__(16) float vals[2][NS * 68];  // 27.2 KB
    __shared__ __align__(16) float lastm[2][NH];
    __shared__ float scores[2][64];
    __shared__ float probs[2][NS];
    __shared__ int   sitem[2 * NS];

    float* rowbase = out + (size_t)b0 * NITEM;
    ulonglong2* mat2 = reinterpret_cast<ulonglong2*>(mat);   // 16B units
    float4*     mat4 = reinterpret_cast<float4*>(mat);

    if (tid >= 192) {
        // ========== zero warps 6-7: prefetch seq_item, zero 2 output rows ==========
        const int t = tid - 192;
        for (int i = t; i < 2 * NS; i += 64) sitem[i] = seq_item[b0 * NS + i];
        float4* row4 = reinterpret_cast<float4*>(rowbase);
        const float4 zf = make_float4(0.f, 0.f, 0.f, 0.f);
        for (int i = t; i < (2 * NITEM) / 4; i += 64) row4[i] = zf;
    } else {
        // ========== compute warps 0-5 ==========
        const int k  = tid & 63;
        const int g  = tid >> 6;          // 0..2 (warp-uniform)
        const int kk = k & 15;            // swizzle key

        // ---- stage xs, lastm, mat <- Wr (swizzled) ----
        const float4* am4 = reinterpret_cast<const float4*>(all_memory + (size_t)b0 * (NS * NH));
        for (int i = tid; i < 2 * NS * NH / 4; i += 192)
            reinterpret_cast<float4*>(xs)[i] = am4[i];
        if (tid < 2 * NH) lastm[tid >> 6][tid & 63] = last_memory[b0 * NH + tid];
        {
            const float4* w4 = reinterpret_cast<const float4*>(Wr);
            for (int i = tid; i < NH * NH / 4; i += 192) {
                int r = i >> 4, j = i & 15;
                mat4[r * 16 + (j ^ (r & 15))] = w4[i];
            }
        }
        asm volatile("bar.sync 1, 192;" ::: "memory");

        // ---- lk[r] = last[r] . Wr[k,:]  via swizzled f32x2 ----
        u64 A0 = pk(0.f, 0.f), A1 = pk(0.f, 0.f), C0 = pk(0.f, 0.f), C1 = pk(0.f, 0.f);
        {
            const ulonglong2* lm0 = reinterpret_cast<const ulonglong2*>(lastm[0]);
            const ulonglong2* lm1 = reinterpret_cast<const ulonglong2*>(lastm[1]);
            #pragma unroll
            for (int i = 0; i < 16; i++) {
                ulonglong2 u = mat2[k * 16 + (i ^ kk)];
                ulonglong2 l0 = lm0[i], l1 = lm1[i];
                fma2(A0, l0.x, u.x);  fma2(A1, l0.y, u.y);
                fma2(C0, l1.x, u.x);  fma2(C1, l1.y, u.y);
            }
        }
        add2(A0, A1); add2(C0, C1);
        const float lk0 = hsum2(A0);
        const float lk1 = hsum2(C0);
        asm volatile("bar.sync 1, 192;" ::: "memory");   // lk reads done

        // ---- restage mat <- Ur (swizzled) ----
        {
            const float4* u4 = reinterpret_cast<const float4*>(Ur);
            for (int i = tid; i < NH * NH / 4; i += 192) {
                int r = i >> 4, j = i & 15;
                mat4[r * 16 + (j ^ (r & 15))] = u4[i];
            }
        }
        asm volatile("bar.sync 1, 192;" ::: "memory");

        const float vk = Vr_w[k];

        // ---- main loop: both rows, ur streamed from swizzled smem ----
        #pragma unroll
        for (int j = 0; j < 17; j++) {
            const int s = 3 * j + g;                     // warp-uniform
            if (s < NS) {
                const ulonglong2* xrA = reinterpret_cast<const ulonglong2*>(xs + s * NH);
                const ulonglong2* xrB = reinterpret_cast<const ulonglong2*>(xs + (NS + s) * NH);
                u64 a0 = pk(lk0, 0.f), a1 = pk(0.f, 0.f);
                u64 c0 = pk(lk1, 0.f), c1 = pk(0.f, 0.f);
                #pragma unroll
                for (int i = 0; i < 16; i++) {
                    ulonglong2 u  = mat2[k * 16 + (i ^ kk)];   // conflict-free LDS.128
                    ulonglong2 wA = xrA[i], wB = xrB[i];       // broadcast LDS.128
                    fma2(a0, wA.x, u.x);
                    fma2(c0, wB.x, u.x);
                    fma2(a1, wA.y, u.y);
                    fma2(c1, wB.y, u.y);
                }
                add2(a0, a1); add2(c0, c1);
                float accA = hsum2(a0), accB = hsum2(c0);
                float eA = __expf(2.0f * accA), eB = __expf(2.0f * accB);
                vals[0][s * 68 + k] = vk * (1.0f - __fdividef(2.0f, eA + 1.0f));
                vals[1][s * 68 + k] = vk * (1.0f - __fdividef(2.0f, eB + 1.0f));
            }
        }
    }
    __syncthreads();   // vals ready; zero STGs CTA-fenced; sitem visible

    // ---- flat reduction over k (all 256 threads; clamped shuffles) ----
    {
        const int s2 = tid >> 2, p = tid & 3;
        const int s2c = (s2 < NS) ? s2 : (NS - 1);
        #pragma unroll
        for (int r = 0; r < 2; r++) {
            const float4* vr = reinterpret_cast<const float4*>(&vals[r][s2c * 68 + p * 16]);
            float4 r0 = vr[0], r1 = vr[1], r2 = vr[2], r3 = vr[3];
            float sum = ((r0.x + r0.y) + (r0.z + r0.w)) + ((r1.x + r1.y) + (r1.z + r1.w))
                      + ((r2.x + r2.y) + (r2.z + r2.w)) + ((r3.x + r3.y) + (r3.z + r3.w));
            sum += __shfl_xor_sync(0xffffffffu, sum, 1);
            sum += __shfl_xor_sync(0xffffffffu, sum, 2);
            if (p == 0 && s2 < NS) scores[r][s2] = sum;
        }
    }
    __syncthreads();

    // ---- softmax: warp 0 -> row 0, warp 1 -> row 1 (Vr_b cancels) ----
    if (tid < 64) {
        const int r = tid >> 5;
        const int t = tid & 31;
        float v0 = (t      < NS) ? scores[r][t]      : -1e30f;
        float v1 = (t + 32 < NS) ? scores[r][t + 32] : -1e30f;
        float m = fmaxf(v0, v1);
        #pragma unroll
        for (int o = 16; o; o >>= 1)
            m = fmaxf(m, __shfl_xor_sync(0xffffffffu, m, o));
        float e0 = (t      < NS) ? __expf(v0 - m) : 0.f;
        float e1 = (t + 32 < NS) ? __expf(v1 - m) : 0.f;
        float ssum = e0 + e1;
        #pragma unroll
        for (int o = 16; o; o >>= 1)
            ssum += __shfl_xor_sync(0xffffffffu, ssum, o);
        float inv = 1.f / ssum;
        if (t      < NS) probs[r][t]      = e0 * inv;
        if (t + 32 < NS) probs[r][t + 32] = e1 * inv;
    }
    __syncthreads();   // probs published; zeros ordered before atomics

    // ---- scatter-add both rows (atomics handle duplicate items) ----
    if (tid < 2 * NS) {
        const int r = (tid < NS) ? 0 : 1;
        const int t = tid - r * NS;
        atomicAdd(rowbase + (size_t)r * NITEM + sitem[tid], probs[r][t]);
    }
}

extern "C" void kernel_launch(void* const* d_in, const int* in_sizes, int n_in,
                              void* d_out, int out_size)
{
    const float* all_memory  = (const float*)d_in[0];
    const float* last_memory = (const float*)d_in[1];
    const int*   seq_item    = (const int*)  d_in[2];
    const float* Wr          = (const float*)d_in[3];
    const float* Ur          = (const float*)d_in[4];
    const float* Vr_w        = (const float*)d_in[5];
    // d_in[6] = Vr_b — softmax shift-invariant, unused.
    float* out = (float*)d_out;

    rrd_all<<<NQ, TPB>>>(all_memory, last_memory, seq_item, Wr, Ur, Vr_w, out);
}

// round 12
// speedup vs baseline: 1.3667x; 1.3667x over previous
#include <cuda_runtime.h>

#define NB 1024
#define NS 50
#define NH 64
#define NITEM 40000
#define TPB 256
#define NQ (NB / 2)       // 512 CTAs, 2 rows each

typedef unsigned long long u64;

__device__ __forceinline__ u64 pk(float lo, float hi) {
    u64 r; asm("mov.b64 %0, {%1, %2};" : "=l"(r) : "f"(lo), "f"(hi)); return r;
}
__device__ __forceinline__ void fma2(u64& d, u64 a, u64 b) {
    asm("fma.rn.f32x2 %0, %1, %2, %0;" : "+l"(d) : "l"(a), "l"(b));
}
__device__ __forceinline__ float hsum2(u64 v) {
    float lo, hi; asm("mov.b64 {%0, %1}, %2;" : "=f"(lo), "=f"(hi) : "l"(v));
    return lo + hi;
}
__device__ __forceinline__ float ftanh(float x) {   // 1 - 2/(e^2x+1)
    float e = __expf(2.0f * x);
    return 1.0f - __fdividef(2.0f, e + 1.0f);
}

__global__ __launch_bounds__(TPB, 2)
void rrd_all(const float* __restrict__ all_memory,
             const float* __restrict__ last_memory,
             const int*   __restrict__ seq_item,
             const float* __restrict__ Wr,
             const float* __restrict__ Ur,
             const float* __restrict__ Vr_w,
             float* __restrict__ out)
{
    const int q   = blockIdx.x;
    const int b0  = 2 * q;
    const int tid = threadIdx.x;

    __shared__ __align__(16) float xs[2 * NS * NH];   // 25.6 KB
    __shared__ __align__(16) float matU[NH * NH];     // 16.4 KB XOR-swizzled float4
    __shared__ __align__(16) float matW[NH * NH];     // 16.4 KB XOR-swizzled float4
    __shared__ __align__(16) float vals[2][NS * 68];  // 27.2 KB
    __shared__ __align__(16) float lastm[2 * NH];
    __shared__ float scores[2][64];
    __shared__ float probs[2][NS];
    __shared__ int   sitem[2 * NS];

    float* rowbase = out + (size_t)b0 * NITEM;
    ulonglong2* matU2 = reinterpret_cast<ulonglong2*>(matU);
    ulonglong2* matW2 = reinterpret_cast<ulonglong2*>(matW);

    // ---- stage everything (all 256 threads) ----
    const float4* am4 = reinterpret_cast<const float4*>(all_memory + (size_t)b0 * (NS * NH));
    for (int i = tid; i < 2 * NS * NH / 4; i += TPB)
        reinterpret_cast<float4*>(xs)[i] = am4[i];
    if (tid < 2 * NH) lastm[tid] = last_memory[b0 * NH + tid];
    if (tid < 2 * NS) sitem[tid] = seq_item[b0 * NS + tid];
    {
        const float4* u4 = reinterpret_cast<const float4*>(Ur);
        const float4* w4 = reinterpret_cast<const float4*>(Wr);
        for (int i = tid; i < NH * NH / 4; i += TPB) {
            int r = i >> 4, j = i & 15;
            int sw = r * 16 + (j ^ (r & 15));         // XOR-swizzled float4 slot
            reinterpret_cast<float4*>(matU)[sw] = u4[i];
            reinterpret_cast<float4*>(matW)[sw] = w4[i];
        }
    }
    __syncthreads();

    if (tid < 128) {
        // ================= compute warps 0-3 =================
        const int w    = tid >> 5;        // warp 0..3
        const int l    = tid & 31;
        const int half = l & 1;           // h-half: [32*half, 32*half+32)
        const int kp   = (w & 1) * 16 + (l >> 1);     // k-pair 0..31
        const int k0   = 2 * kp, k1 = k0 + 1;
        const int sp   = w >> 1;          // s parity (warps 0,1: even s; 2,3: odd)
        const int j0   = 8 * half;        // float4 offset of h-half

        // ---- register fill: Ur rows k0,k1 (h-half), swizzle-indexed ----
        u64 urp[16], urq[16];
        #pragma unroll
        for (int jj = 0; jj < 8; jj++) {
            ulonglong2 t0 = matU2[k0 * 16 + ((j0 + jj) ^ (k0 & 15))];
            ulonglong2 t1 = matU2[k1 * 16 + ((j0 + jj) ^ (k1 & 15))];
            urp[2 * jj] = t0.x; urp[2 * jj + 1] = t0.y;
            urq[2 * jj] = t1.x; urq[2 * jj + 1] = t1.y;
        }
        const float vk0 = Vr_w[k0], vk1 = Vr_w[k1];

        // ---- lk: same streamed pattern over Wr rows + lastm ----
        u64 pA0 = 0, pA1 = 0, pB0 = 0, pB1 = 0;
        {
            const ulonglong2* lmA = reinterpret_cast<const ulonglong2*>(lastm + 32 * half);
            const ulonglong2* lmB = reinterpret_cast<const ulonglong2*>(lastm + NH + 32 * half);
            #pragma unroll
            for (int jj = 0; jj < 8; jj++) {
                ulonglong2 w0 = matW2[k0 * 16 + ((j0 + jj) ^ (k0 & 15))];
                ulonglong2 w1 = matW2[k1 * 16 + ((j0 + jj) ^ (k1 & 15))];
                ulonglong2 la = lmA[jj], lb = lmB[jj];
                fma2(pA0, la.x, w0.x); fma2(pA0, la.y, w0.y);
                fma2(pA1, la.x, w1.x); fma2(pA1, la.y, w1.y);
                fma2(pB0, lb.x, w0.x); fma2(pB0, lb.y, w0.y);
                fma2(pB1, lb.x, w1.x); fma2(pB1, lb.y, w1.y);
            }
        }
        float lkA0 = hsum2(pA0), lkA1 = hsum2(pA1);
        float lkB0 = hsum2(pB0), lkB1 = hsum2(pB1);
        lkA0 += __shfl_xor_sync(0xffffffffu, lkA0, 1);   // combine h-halves
        lkA1 += __shfl_xor_sync(0xffffffffu, lkA1, 1);
        lkB0 += __shfl_xor_sync(0xffffffffu, lkB0, 1);
        lkB1 += __shfl_xor_sync(0xffffffffu, lkB1, 1);

        // ---- main loop: 25 s-iters; 16 LDS feed 64 fma2 (1:4) ----
        #pragma unroll
        for (int j = 0; j < 25; j++) {
            const int s = 2 * j + sp;
            const ulonglong2* xrA = reinterpret_cast<const ulonglong2*>(xs + s * NH + 32 * half);
            const ulonglong2* xrB = reinterpret_cast<const ulonglong2*>(xs + (NS + s) * NH + 32 * half);
            u64 aA0 = 0, aA1 = 0, aB0 = 0, aB1 = 0;
            #pragma unroll
            for (int i = 0; i < 8; i++) {
                ulonglong2 wA = xrA[i], wB = xrB[i];
                fma2(aA0, wA.x, urp[2 * i]); fma2(aA0, wA.y, urp[2 * i + 1]);
                fma2(aA1, wA.x, urq[2 * i]); fma2(aA1, wA.y, urq[2 * i + 1]);
                fma2(aB0, wB.x, urp[2 * i]); fma2(aB0, wB.y, urp[2 * i + 1]);
                fma2(aB1, wB.x, urq[2 * i]); fma2(aB1, wB.y, urq[2 * i + 1]);
            }
            float sA0 = hsum2(aA0), sA1 = hsum2(aA1);
            float sB0 = hsum2(aB0), sB1 = hsum2(aB1);
            sA0 += __shfl_xor_sync(0xffffffffu, sA0, 1);
            sA1 += __shfl_xor_sync(0xffffffffu, sA1, 1);
            sB0 += __shfl_xor_sync(0xffffffffu, sB0, 1);
            sB1 += __shfl_xor_sync(0xffffffffu, sB1, 1);
            // even lane -> row A, odd lane -> row B (uniform, no branch)
            float x0 = half ? (sB0 + lkB0) : (sA0 + lkA0);
            float x1 = half ? (sB1 + lkB1) : (sA1 + lkA1);
            float2 tv = make_float2(vk0 * ftanh(x0), vk1 * ftanh(x1));
            *reinterpret_cast<float2*>(&vals[half][s * 68 + k0]) = tv;
        }
    } else {
        // ================= zero warps 4-7: this CTA's 2 output rows =========
        float4* row4 = reinterpret_cast<float4*>(rowbase);
        const float4 zf = make_float4(0.f, 0.f, 0.f, 0.f);
        for (int i = tid - 128; i < (2 * NITEM) / 4; i += 128)
            row4[i] = zf;
    }
    __syncthreads();   // vals ready; zero STGs CTA-ordered

    // ---- reduction over k: thread (s2, r, p) sums 32; shfl combine halves ----
    {
        const int s2 = tid >> 2;                  // 0..63
        const int r  = (tid >> 1) & 1;            // row
        const int p  = tid & 1;                   // k-half
        const int s2c = (s2 < NS) ? s2 : (NS - 1);
        const float4* vr = reinterpret_cast<const float4*>(&vals[r][s2c * 68 + p * 32]);
        float4 r0 = vr[0], r1 = vr[1], r2 = vr[2], r3 = vr[3];
        float4 r4 = vr[4], r5 = vr[5], r6 = vr[6], r7 = vr[7];
        float sum = (((r0.x + r0.y) + (r0.z + r0.w)) + ((r1.x + r1.y) + (r1.z + r1.w)))
                  + (((r2.x + r2.y) + (r2.z + r2.w)) + ((r3.x + r3.y) + (r3.z + r3.w)))
                  + (((r4.x + r4.y) + (r4.z + r4.w)) + ((r5.x + r5.y) + (r5.z + r5.w)))
                  + (((r6.x + r6.y) + (r6.z + r6.w)) + ((r7.x + r7.y) + (r7.z + r7.w)));
        sum += __shfl_xor_sync(0xffffffffu, sum, 1);
        if (p == 0 && s2 < NS) scores[r][s2] = sum;
    }
    __syncthreads();

    // ---- softmax: warp 0 -> row 0, warp 1 -> row 1 (Vr_b cancels) ----
    if (tid < 64) {
        const int r = tid >> 5;
        const int t = tid & 31;
        float v0 = (t      < NS) ? scores[r][t]      : -1e30f;
        float v1 = (t + 32 < NS) ? scores[r][t + 32] : -1e30f;
        float m = fmaxf(v0, v1);
        #pragma unroll
        for (int o = 16; o; o >>= 1)
            m = fmaxf(m, __shfl_xor_sync(0xffffffffu, m, o));
        float e0 = (t      < NS) ? __expf(v0 - m) : 0.f;
        float e1 = (t + 32 < NS) ? __expf(v1 - m) : 0.f;
        float ssum = e0 + e1;
        #pragma unroll
        for (int o = 16; o; o >>= 1)
            ssum += __shfl_xor_sync(0xffffffffu, ssum, o);
        float inv = 1.f / ssum;
        if (t      < NS) probs[r][t]      = e0 * inv;
        if (t + 32 < NS) probs[r][t + 32] = e1 * inv;
    }
    __syncthreads();   // probs published; zeros ordered before atomics

    // ---- scatter-add both rows ----
    if (tid < 2 * NS) {
        const int r = (tid < NS) ? 0 : 1;
        const int t = tid - r * NS;
        atomicAdd(rowbase + (size_t)r * NITEM + sitem[tid], probs[r][t]);
    }
}

extern "C" void kernel_launch(void* const* d_in, const int* in_sizes, int n_in,
                              void* d_out, int out_size)
{
    const float* all_memory  = (const float*)d_in[0];
    const float* last_memory = (const float*)d_in[1];
    const int*   seq_item    = (const int*)  d_in[2];
    const float* Wr          = (const float*)d_in[3];
    const float* Ur          = (const float*)d_in[4];
    const float* Vr_w        = (const float*)d_in[5];
    // d_in[6] = Vr_b — softmax shift-invariant, unused.
    float* out = (float*)d_out;

    rrd_all<<<NQ, TPB>>>(all_memory, last_memory, seq_item, Wr, Ur, Vr_w, out);
}

// round 13
// speedup vs baseline: 1.6235x; 1.1879x over previous
#include <cuda_runtime.h>

#define NB 1024
#define NS 50
#define NH 64
#define NITEM 40000
#define TPB 256
#define NQ (NB / 2)           // 512 CTAs, 2 rows each
#define ZBYTES 16000          // zero smem buffer; 20 * 16000 = 320000 B = 2 rows
#define NBULK 20

typedef unsigned long long u64;

__device__ __forceinline__ u64 pk(float lo, float hi) {
    u64 r; asm("mov.b64 %0, {%1, %2};" : "=l"(r) : "f"(lo), "f"(hi)); return r;
}
__device__ __forceinline__ void fma2(u64& d, u64 a, u64 b) {
    asm("fma.rn.f32x2 %0, %1, %2, %0;" : "+l"(d) : "l"(a), "l"(b));
}
__device__ __forceinline__ void add2(u64& d, u64 a) {
    asm("add.rn.f32x2 %0, %1, %0;" : "+l"(d) : "l"(a));
}
__device__ __forceinline__ float hsum2(u64 v) {
    float lo, hi; asm("mov.b64 {%0, %1}, %2;" : "=f"(lo), "=f"(hi) : "l"(v));
    return lo + hi;
}
__device__ __forceinline__ unsigned smem_u32(const void* p) {
    unsigned a;
    asm("{ .reg .u64 t; cvta.to.shared.u64 t, %1; cvt.u32.u64 %0, t; }" : "=r"(a) : "l"(p));
    return a;
}

__global__ __launch_bounds__(TPB, 2)
void rrd_all(const float* __restrict__ all_memory,
             const float* __restrict__ last_memory,
             const int*   __restrict__ seq_item,
             const float* __restrict__ Wr,
             const float* __restrict__ Ur,
             const float* __restrict__ Vr_w,
             float* __restrict__ out)
{
    const int q   = blockIdx.x;
    const int b0  = 2 * q;
    const int tid = threadIdx.x;

    __shared__ __align__(16) float xs[2 * NS * NH];   // 25.6 KB
    __shared__ float matW[NH * 65];                   // 16.6 KB pad-65
    __shared__ float matU[NH * 65];                   // 16.6 KB
    __shared__ __align__(16) float vals[2][NS * 68];  // 27.2 KB
    __shared__ __align__(16) float zbuf[ZBYTES / 4];  // 15.6 KB of zeros (TMA source)
    __shared__ float lastm[2][NH];
    __shared__ float scores[2][64];
    __shared__ float probs[2][NS];
    __shared__ int   sitem[2 * NS];

    float* rowbase = out + (size_t)b0 * NITEM;

    // ---- stage everything + zero the TMA source buffer ----
    const float4* am4 = reinterpret_cast<const float4*>(all_memory + (size_t)b0 * (NS * NH));
    for (int i = tid; i < 2 * NS * NH / 4; i += TPB)
        reinterpret_cast<float4*>(xs)[i] = am4[i];
    if (tid < 2 * NH) lastm[tid >> 6][tid & 63] = last_memory[b0 * NH + tid];
    if (tid < 2 * NS) sitem[tid] = seq_item[b0 * NS + tid];
    {
        const float4 zf = make_float4(0.f, 0.f, 0.f, 0.f);
        for (int i = tid; i < ZBYTES / 16; i += TPB)
            reinterpret_cast<float4*>(zbuf)[i] = zf;
    }
    {
        const float4* w4 = reinterpret_cast<const float4*>(Wr);
        const float4* u4 = reinterpret_cast<const float4*>(Ur);
        for (int i = tid; i < NH * NH / 4; i += TPB) {
            int r = i >> 4, c = (i & 15) * 4;
            float4 w = w4[i], u = u4[i];
            float* dw = &matW[r * 65 + c];
            dw[0] = w.x; dw[1] = w.y; dw[2] = w.z; dw[3] = w.w;
            float* du = &matU[r * 65 + c];
            du[0] = u.x; du[1] = u.y; du[2] = u.z; du[3] = u.w;
        }
    }
    __syncthreads();

    // ---- thread 0: fire 20 async bulk zero-stores (TMA engine drains them) ----
    if (tid == 0) {
        unsigned zsrc = smem_u32(zbuf);
        asm volatile("fence.proxy.async.shared::cta;" ::: "memory");
        char* gdst = reinterpret_cast<char*>(rowbase);
        #pragma unroll
        for (int c = 0; c < NBULK; c++) {
            asm volatile(
                "cp.async.bulk.global.shared::cta.bulk_group [%0], [%1], %2;"
                :: "l"(gdst + (size_t)c * ZBYTES), "r"(zsrc), "r"(ZBYTES)
                : "memory");
        }
        asm volatile("cp.async.bulk.commit_group;" ::: "memory");
    }

    // ================= compute: ALL 8 warps =================
    {
        const int k = tid & 63;
        const int g = tid >> 6;          // 0..3 (warp-uniform)

        // lk[r] = sum_h last[r][h]*Wr[k,h]
        float lkA0 = 0.f, lkA1 = 0.f, lkB0 = 0.f, lkB1 = 0.f;
        #pragma unroll
        for (int h = 0; h < NH; h += 2) {
            float w0 = matW[k * 65 + h], w1 = matW[k * 65 + h + 1];
            lkA0 += lastm[0][h] * w0;  lkA1 += lastm[0][h + 1] * w1;
            lkB0 += lastm[1][h] * w0;  lkB1 += lastm[1][h + 1] * w1;
        }
        const float lk0 = lkA0 + lkA1;
        const float lk1 = lkB0 + lkB1;

        // Ur row k packed (reused for both rows)
        u64 urp[NH / 2];
        #pragma unroll
        for (int h = 0; h < NH / 2; h++)
            urp[h] = pk(matU[k * 65 + 2 * h], matU[k * 65 + 2 * h + 1]);
        const float vk = Vr_w[k];

        #pragma unroll
        for (int j = 0; j < 13; j++) {
            const int s = 4 * j + g;                 // warp-uniform
            if (s < NS) {
                const ulonglong2* xrA = reinterpret_cast<const ulonglong2*>(xs + s * NH);
                const ulonglong2* xrB = reinterpret_cast<const ulonglong2*>(xs + (NS + s) * NH);
                u64 a0 = pk(lk0, 0.f), a1 = pk(0.f, 0.f);
                u64 c0 = pk(lk1, 0.f), c1 = pk(0.f, 0.f);
                #pragma unroll
                for (int i = 0; i < 16; i++) {
                    ulonglong2 wA = xrA[i], wB = xrB[i];
                    fma2(a0, wA.x, urp[2 * i]);
                    fma2(c0, wB.x, urp[2 * i]);
                    fma2(a1, wA.y, urp[2 * i + 1]);
                    fma2(c1, wB.y, urp[2 * i + 1]);
                }
                add2(a0, a1); add2(c0, c1);
                float accA = hsum2(a0), accB = hsum2(c0);
                float eA = __expf(2.0f * accA), eB = __expf(2.0f * accB);
                vals[0][s * 68 + k] = vk * (1.0f - __fdividef(2.0f, eA + 1.0f));
                vals[1][s * 68 + k] = vk * (1.0f - __fdividef(2.0f, eB + 1.0f));
            }
        }
    }
    __syncthreads();   // vals ready

    // ---- flat reduction over k (all 256 threads; clamped shuffles) ----
    {
        const int s2 = tid >> 2, p = tid & 3;
        const int s2c = (s2 < NS) ? s2 : (NS - 1);
        #pragma unroll
        for (int r = 0; r < 2; r++) {
            const float4* vr = reinterpret_cast<const float4*>(&vals[r][s2c * 68 + p * 16]);
            float4 r0 = vr[0], r1 = vr[1], r2 = vr[2], r3 = vr[3];
            float sum = ((r0.x + r0.y) + (r0.z + r0.w)) + ((r1.x + r1.y) + (r1.z + r1.w))
                      + ((r2.x + r2.y) + (r2.z + r2.w)) + ((r3.x + r3.y) + (r3.z + r3.w));
            sum += __shfl_xor_sync(0xffffffffu, sum, 1);
            sum += __shfl_xor_sync(0xffffffffu, sum, 2);
            if (p == 0 && s2 < NS) scores[r][s2] = sum;
        }
    }
    __syncthreads();

    // ---- softmax: warp 0 -> row 0, warp 1 -> row 1 (Vr_b cancels) ----
    if (tid < 64) {
        const int r = tid >> 5;
        const int t = tid & 31;
        float v0 = (t      < NS) ? scores[r][t]      : -1e30f;
        float v1 = (t + 32 < NS) ? scores[r][t + 32] : -1e30f;
        float m = fmaxf(v0, v1);
        #pragma unroll
        for (int o = 16; o; o >>= 1)
            m = fmaxf(m, __shfl_xor_sync(0xffffffffu, m, o));
        float e0 = (t      < NS) ? __expf(v0 - m) : 0.f;
        float e1 = (t + 32 < NS) ? __expf(v1 - m) : 0.f;
        float ssum = e0 + e1;
        #pragma unroll
        for (int o = 16; o; o >>= 1)
            ssum += __shfl_xor_sync(0xffffffffu, ssum, o);
        float inv = 1.f / ssum;
        if (t      < NS) probs[r][t]      = e0 * inv;
        if (t + 32 < NS) probs[r][t + 32] = e1 * inv;
    }

    // ---- issuing thread drains the bulk zero-stores before atomics ----
    if (tid == 0)
        asm volatile("cp.async.bulk.wait_group 0;" ::: "memory");
    __syncthreads();   // probs published; zeros complete & ordered before atomics

    // ---- scatter-add both rows (atomics handle duplicate items) ----
    if (tid < 2 * NS) {
        const int r = (tid < NS) ? 0 : 1;
        const int t = tid - r * NS;
        atomicAdd(rowbase + (size_t)r * NITEM + sitem[tid], probs[r][t]);
    }
}

extern "C" void kernel_launch(void* const* d_in, const int* in_sizes, int n_in,
                              void* d_out, int out_size)
{
    const float* all_memory  = (const float*)d_in[0];
    const float* last_memory = (const float*)d_in[1];
    const int*   seq_item    = (const int*)  d_in[2];
    const float* Wr          = (const float*)d_in[3];
    const float* Ur          = (const float*)d_in[4];
    const float* Vr_w        = (const float*)d_in[5];
    // d_in[6] = Vr_b — softmax shift-invariant, unused.
    float* out = (float*)d_out;

    rrd_all<<<NQ, TPB>>>(all_memory, last_memory, seq_item, Wr, Ur, Vr_w, out);
}